// round 2
// baseline (speedup 1.0000x reference)
#include <cuda_runtime.h>
#include <cstdint>

// Problem constants
#define Bdim   8
#define Cdim   64
#define Ndim   40962
#define Kn     7
#define KN     (Kn * Ndim)
#define OUTd   64
#define TN     128                    // n-tile per CTA
#define NTILES ((Ndim + TN - 1) / TN) // 321

// Smem B-fragment chunk layout: addr = kk*SKK + t*64 + r*32 + lane   (floats)
#define SKK     1032                  // 16*64 + 8 pad (bank decorrelation)
#define CHUNK_F (8 * SKK)             // 8256 floats per k-neighbor chunk
#define WP_F    28672                 // 4 mb * 56 ksteps * 32 lanes * 4 regs
#define SMEM_BYTES ((WP_F + 2 * CHUNK_F) * 4 + 896 * 4)

// Scratch (device globals; allocation-free rule). 16B-aligned for cp.async.
__device__ __align__(256) float g_xt[(size_t)Bdim * Ndim * Cdim];
__device__ __align__(256) float g_wp[WP_F];
__device__ __align__(256) int   g_idx[KN];

__device__ __forceinline__ float tf32r(float x) {
    uint32_t u;
    asm("cvt.rna.tf32.f32 %0, %1;" : "=r"(u) : "f"(x));
    return __uint_as_float(u);
}

// ---------------------------------------------------------------------------
// Kernel 0: normalize neighbor indices (int32 OR int64 input) -> g_idx int32.
// Each block independently detects dtype: scan first 4096 int32 words; if the
// buffer is int64 every odd word is a zero high-half; an int32 buffer of
// random indices cannot have 2048 consecutive zero odd words.
// ---------------------------------------------------------------------------
__global__ void idx_normalize(const void* __restrict__ neigh) {
    __shared__ int s_is64;
    const int* p32 = (const int*)neigh;
    int tid = threadIdx.x;
    unsigned acc = 0;
#pragma unroll
    for (int q = 0; q < 8; q++) acc |= (unsigned)p32[2 * (tid + 256 * q) + 1];
#pragma unroll
    for (int o = 16; o > 0; o >>= 1) acc |= __shfl_down_sync(~0u, acc, o);
    if (tid == 0) s_is64 = 1;
    __syncthreads();
    if ((tid & 31) == 0 && acc != 0) s_is64 = 0;   // nonzero odd word -> int32
    __syncthreads();
    int is64 = s_is64;

    const long long* p64 = (const long long*)neigh;
    for (int i = blockIdx.x * 256 + tid; i < KN; i += gridDim.x * 256)
        g_idx[i] = is64 ? (int)p64[i] : p32[i];
}

// ---------------------------------------------------------------------------
// Kernel 1: transpose x [B, C=64, N] -> g_xt [B, N, C], rounding to tf32.
// ---------------------------------------------------------------------------
__global__ void transpose_tf32(const float* __restrict__ x) {
    __shared__ float tile[32][33];
    int b  = blockIdx.z;
    int c0 = blockIdx.y * 32;
    int n0 = blockIdx.x * 32;
    int tx = threadIdx.x, ty = threadIdx.y;

    const float* xb = x + (size_t)b * Cdim * Ndim;
#pragma unroll
    for (int r = 0; r < 4; r++) {
        int c = c0 + ty + r * 8;
        int n = n0 + tx;
        tile[ty + r * 8][tx] = (n < Ndim) ? xb[(size_t)c * Ndim + n] : 0.f;
    }
    __syncthreads();
    float* xtb = g_xt + (size_t)b * Ndim * Cdim;
#pragma unroll
    for (int r = 0; r < 4; r++) {
        int n = n0 + ty + r * 8;
        int c = c0 + tx;
        if (n < Ndim) xtb[(size_t)n * Cdim + c] = tf32r(tile[tx][ty + r * 8]);
    }
}

// ---------------------------------------------------------------------------
// Kernel 2: permute W [64, 448] into A-fragment-ready layout (tf32-rounded).
// g_wp[((mb*56 + kk)*32 + lane)*4 + q] where
//   q=0: (row, col) = (mb*16 + lane/4,      kk*8 + lane%4)
//   q=1:             (mb*16 + lane/4 + 8,   kk*8 + lane%4)
//   q=2:             (mb*16 + lane/4,       kk*8 + lane%4 + 4)
//   q=3:             (mb*16 + lane/4 + 8,   kk*8 + lane%4 + 4)
// ---------------------------------------------------------------------------
__global__ void wprep_kernel(const float* __restrict__ W) {
    int i = blockIdx.x * 256 + threadIdx.x;
    if (i >= WP_F) return;
    int q  = i & 3;
    int l  = (i >> 2) & 31;
    int kk = (i >> 7) % 56;
    int mb = (i >> 7) / 56;
    int row = mb * 16 + (l >> 2) + (q & 1) * 8;
    int col = kk * 8 + (l & 3) + ((q >> 1) & 1) * 4;
    g_wp[i] = tf32r(W[row * (Kn * Cdim) + col]);
}

// ---------------------------------------------------------------------------
// Kernel 3: fused gather + tf32 GEMM
// ---------------------------------------------------------------------------
__device__ __forceinline__ void cp16(void* dst, const void* src) {
    uint32_t d = (uint32_t)__cvta_generic_to_shared(dst);
    asm volatile("cp.async.cg.shared.global [%0], [%1], 16;\n" ::"r"(d), "l"(src));
}

// Gather one neighbor chunk (k) for the 128-n tile into B-fragment layout.
// Each gathered float4 (n_local, c=4j..4j+3) lands at exactly one 16B slot:
//   kk = j/2, t = n_local/8, r = j&1, lane = 4*(n_local&7) + i
__device__ __forceinline__ void gather_chunk(const float* __restrict__ xb,
                                             const int* __restrict__ idx_s,
                                             int k, float* __restrict__ buf,
                                             int tid) {
#pragma unroll
    for (int p = 0; p < 8; p++) {
        int e  = tid + 256 * p;       // 0..2047
        int nl = e >> 4;              // row within tile
        int j  = e & 15;              // float4 index within row
        int g  = idx_s[nl * Kn + k];
        const float* src = xb + ((size_t)g << 6) + (j << 2);
        float* dst = buf + (j >> 1) * SKK + (nl >> 3) * 64 + (j & 1) * 32 +
                     ((nl & 7) << 2);
        cp16(dst, src);
    }
}

__device__ __forceinline__ void mma8(float* d, uint32_t a0, uint32_t a1,
                                     uint32_t a2, uint32_t a3, uint32_t b0,
                                     uint32_t b1) {
    asm volatile(
        "mma.sync.aligned.m16n8k8.row.col.f32.tf32.tf32.f32 "
        "{%0,%1,%2,%3}, {%4,%5,%6,%7}, {%8,%9}, {%0,%1,%2,%3};\n"
        : "+f"(d[0]), "+f"(d[1]), "+f"(d[2]), "+f"(d[3])
        : "r"(a0), "r"(a1), "r"(a2), "r"(a3), "r"(b0), "r"(b1));
}

__device__ __forceinline__ void compute_chunk(const float* __restrict__ Wp_s,
                                              const float* __restrict__ buf,
                                              int k, int wm, int wn, int lane,
                                              float d[2][4][4]) {
#pragma unroll
    for (int kk = 0; kk < 8; kk++) {
        int ks = k * 8 + kk;
        const uint4 A0 = *reinterpret_cast<const uint4*>(
            Wp_s + (((2 * wm + 0) * 56 + ks) * 32 + lane) * 4);
        const uint4 A1 = *reinterpret_cast<const uint4*>(
            Wp_s + (((2 * wm + 1) * 56 + ks) * 32 + lane) * 4);
        uint32_t b0[4], b1[4];
#pragma unroll
        for (int tt = 0; tt < 4; tt++) {
            const float* p = buf + kk * SKK + (wn * 4 + tt) * 64 + lane;
            b0[tt] = __float_as_uint(p[0]);
            b1[tt] = __float_as_uint(p[32]);
        }
#pragma unroll
        for (int tt = 0; tt < 4; tt++) {
            mma8(d[0][tt], A0.x, A0.y, A0.z, A0.w, b0[tt], b1[tt]);
            mma8(d[1][tt], A1.x, A1.y, A1.z, A1.w, b0[tt], b1[tt]);
        }
    }
}

__global__ __launch_bounds__(256, 1) void fused_kernel(
    const float* __restrict__ bias, float* __restrict__ out) {
    extern __shared__ float sm[];
    float* Wp_s = sm;
    float* bp0  = sm + WP_F;
    float* bp1  = bp0 + CHUNK_F;
    int*   idx_s = (int*)(bp1 + CHUNK_F);

    int tid  = threadIdx.x;
    int lane = tid & 31;
    int w    = tid >> 5;
    int wm   = w & 1;   // M half (32 rows)
    int wn   = w >> 1;  // N quarter (32 cols)
    int b    = blockIdx.y;
    int n0   = blockIdx.x * TN;
    const float* xb = g_xt + (size_t)b * Ndim * Cdim;

    // Load this tile's neighbor indices into smem.
    for (int e = tid; e < TN * Kn; e += 256) {
        int gi = n0 * Kn + e;
        idx_s[e] = (gi < KN) ? g_idx[gi] : 0;
    }
    __syncthreads();

    // Group 0: W fragments + chunk 0;  Group 1: chunk 1
#pragma unroll
    for (int q = 0; q < 28; q++) {
        int e = tid + 256 * q;  // 0..7167 float4s
        cp16(Wp_s + e * 4, g_wp + e * 4);
    }
    gather_chunk(xb, idx_s, 0, bp0, tid);
    asm volatile("cp.async.commit_group;\n");
    gather_chunk(xb, idx_s, 1, bp1, tid);
    asm volatile("cp.async.commit_group;\n");
    asm volatile("cp.async.wait_group 1;\n");
    __syncthreads();

    float d[2][4][4];
#pragma unroll
    for (int i = 0; i < 2; i++)
#pragma unroll
        for (int j = 0; j < 4; j++)
#pragma unroll
            for (int q = 0; q < 4; q++) d[i][j][q] = 0.f;

    for (int k = 0; k < Kn; k++) {
        const float* buf = (k & 1) ? bp1 : bp0;
        compute_chunk(Wp_s, buf, k, wm, wn, lane, d);
        __syncthreads();
        if (k + 2 < Kn) {
            float* nbuf = (k & 1) ? bp1 : bp0;  // just-freed buffer
            gather_chunk(xb, idx_s, k + 2, nbuf, tid);
            asm volatile("cp.async.commit_group;\n");
            asm volatile("cp.async.wait_group 1;\n");  // chunk k+1 complete
            __syncthreads();
        } else if (k + 1 < Kn) {
            asm volatile("cp.async.wait_group 0;\n");  // last chunk complete
            __syncthreads();
        }
    }

    // Epilogue: add bias, write out[b, o, n]
#pragma unroll
    for (int mb2 = 0; mb2 < 2; mb2++) {
        int o = wm * 32 + mb2 * 16 + (lane >> 2);
        float bv0 = bias[o];
        float bv1 = bias[o + 8];
        float* op0 = out + ((size_t)(b * OUTd + o)) * Ndim;
        float* op1 = op0 + (size_t)8 * Ndim;
#pragma unroll
        for (int tt = 0; tt < 4; tt++) {
            int nb = n0 + wn * 32 + tt * 8 + 2 * (lane & 3);
            if (nb < Ndim) {
                float v0 = d[mb2][tt][0] + bv0;
                float v1 = d[mb2][tt][1] + bv0;
                float v2 = d[mb2][tt][2] + bv1;
                float v3 = d[mb2][tt][3] + bv1;
                if (nb + 1 < Ndim) {
                    *reinterpret_cast<float2*>(op0 + nb) = make_float2(v0, v1);
                    *reinterpret_cast<float2*>(op1 + nb) = make_float2(v2, v3);
                } else {
                    op0[nb] = v0;
                    op1[nb] = v2;
                }
            }
        }
    }
}

// ---------------------------------------------------------------------------
// Launch
// ---------------------------------------------------------------------------
extern "C" void kernel_launch(void* const* d_in, const int* in_sizes, int n_in,
                              void* d_out, int out_size) {
    const float* x     = (const float*)d_in[0];
    const void*  neigh = d_in[1];          // int32 OR int64 (jax x64 trap)
    const float* W     = (const float*)d_in[2];
    const float* bias  = (const float*)d_in[3];
    float*       out   = (float*)d_out;

    cudaFuncSetAttribute(fused_kernel,
                         cudaFuncAttributeMaxDynamicSharedMemorySize,
                         SMEM_BYTES);

    idx_normalize<<<280, 256>>>(neigh);
    transpose_tf32<<<dim3((Ndim + 31) / 32, Cdim / 32, Bdim), dim3(32, 8)>>>(x);
    wprep_kernel<<<(WP_F + 255) / 256, 256>>>(W);
    fused_kernel<<<dim3(NTILES, Bdim), 256, SMEM_BYTES>>>(bias, out);
}

// round 3
// speedup vs baseline: 1.1393x; 1.1393x over previous
#include <cuda_runtime.h>
#include <cstdint>

// Problem constants
#define Bdim   8
#define Cdim   64
#define Ndim   40962
#define Kn     7
#define KN     (Kn * Ndim)
#define OUTd   64
#define TN     128                    // n-tile per CTA
#define NTILES ((Ndim + TN - 1) / TN) // 321

// Smem B-fragment chunk layout: addr = kk*SKK + t*64 + r*32 + lane   (floats)
#define SKK     1032                  // 16*64 + 8 pad (bank decorrelation)
#define CHUNK_F (8 * SKK)             // 8256 floats per k-neighbor chunk
#define WP_F    28672                 // 4 mb * 56 ksteps * 32 lanes * 4 regs
#define SMEM_BYTES ((2 * CHUNK_F) * 4 + 896 * 4)   // 69,632 B -> 2 CTAs/SM

// Scratch (device globals; allocation-free rule). 16B-aligned for cp.async/LDG.128.
__device__ __align__(256) float g_xt[(size_t)Bdim * Ndim * Cdim];
__device__ __align__(256) float g_wp[WP_F];
__device__ __align__(256) int   g_idx[KN];

__device__ __forceinline__ float tf32r(float x) {
    uint32_t u;
    asm("cvt.rna.tf32.f32 %0, %1;" : "=r"(u) : "f"(x));
    return __uint_as_float(u);
}

// ---------------------------------------------------------------------------
// Kernel 0: normalize neighbor indices (int32 OR int64 input) -> g_idx int32.
// Dtype detected per-block: for int64 input every odd int32 word is a zero
// high-half; random int32 indices cannot produce 2048 consecutive zero odd
// words. Deterministic, no cross-block communication.
// ---------------------------------------------------------------------------
__global__ void idx_normalize(const void* __restrict__ neigh) {
    __shared__ int s_is64;
    const int* p32 = (const int*)neigh;
    int tid = threadIdx.x;
    unsigned acc = 0;
#pragma unroll
    for (int q = 0; q < 8; q++) acc |= (unsigned)p32[2 * (tid + 256 * q) + 1];
#pragma unroll
    for (int o = 16; o > 0; o >>= 1) acc |= __shfl_down_sync(~0u, acc, o);
    if (tid == 0) s_is64 = 1;
    __syncthreads();
    if ((tid & 31) == 0 && acc != 0) s_is64 = 0;
    __syncthreads();
    int is64 = s_is64;

    const long long* p64 = (const long long*)neigh;
    for (int i = blockIdx.x * 256 + tid; i < KN; i += gridDim.x * 256)
        g_idx[i] = is64 ? (int)p64[i] : p32[i];
}

// ---------------------------------------------------------------------------
// Kernel 1: transpose x [B, C=64, N] -> g_xt [B, N, C], rounding to tf32.
// ---------------------------------------------------------------------------
__global__ void transpose_tf32(const float* __restrict__ x) {
    __shared__ float tile[32][33];
    int b  = blockIdx.z;
    int c0 = blockIdx.y * 32;
    int n0 = blockIdx.x * 32;
    int tx = threadIdx.x, ty = threadIdx.y;

    const float* xb = x + (size_t)b * Cdim * Ndim;
#pragma unroll
    for (int r = 0; r < 4; r++) {
        int c = c0 + ty + r * 8;
        int n = n0 + tx;
        tile[ty + r * 8][tx] = (n < Ndim) ? xb[(size_t)c * Ndim + n] : 0.f;
    }
    __syncthreads();
    float* xtb = g_xt + (size_t)b * Ndim * Cdim;
#pragma unroll
    for (int r = 0; r < 4; r++) {
        int n = n0 + ty + r * 8;
        int c = c0 + tx;
        if (n < Ndim) xtb[(size_t)n * Cdim + c] = tf32r(tile[tx][ty + r * 8]);
    }
}

// ---------------------------------------------------------------------------
// Kernel 2: permute W [64, 448] into A-fragment-ready layout (tf32-rounded).
// g_wp[((mb*56 + kk)*32 + lane)*4 + q] where
//   q=0: (row, col) = (mb*16 + lane/4,      kk*8 + lane%4)
//   q=1:             (mb*16 + lane/4 + 8,   kk*8 + lane%4)
//   q=2:             (mb*16 + lane/4,       kk*8 + lane%4 + 4)
//   q=3:             (mb*16 + lane/4 + 8,   kk*8 + lane%4 + 4)
// ---------------------------------------------------------------------------
__global__ void wprep_kernel(const float* __restrict__ W) {
    int i = blockIdx.x * 256 + threadIdx.x;
    if (i >= WP_F) return;
    int q  = i & 3;
    int l  = (i >> 2) & 31;
    int kk = (i >> 7) % 56;
    int mb = (i >> 7) / 56;
    int row = mb * 16 + (l >> 2) + (q & 1) * 8;
    int col = kk * 8 + (l & 3) + ((q >> 1) & 1) * 4;
    g_wp[i] = tf32r(W[row * (Kn * Cdim) + col]);
}

// ---------------------------------------------------------------------------
// Kernel 3: fused gather + tf32 GEMM.  A fragments stream from g_wp via L1
// (shared by all CTAs); smem holds only the double-buffered gather chunks,
// allowing 2 CTAs/SM (25% occupancy).
// ---------------------------------------------------------------------------
__device__ __forceinline__ void cp16(void* dst, const void* src) {
    uint32_t d = (uint32_t)__cvta_generic_to_shared(dst);
    asm volatile("cp.async.cg.shared.global [%0], [%1], 16;\n" ::"r"(d), "l"(src));
}

// Gather one neighbor chunk (k) for the 128-n tile into B-fragment layout.
// Each gathered float4 (n_local, c=4j..4j+3) lands at exactly one 16B slot:
//   kk = j/2, t = n_local/8, r = j&1, lane = 4*(n_local&7) + i
__device__ __forceinline__ void gather_chunk(const float* __restrict__ xb,
                                             const int* __restrict__ idx_s,
                                             int k, float* __restrict__ buf,
                                             int tid) {
#pragma unroll
    for (int p = 0; p < 8; p++) {
        int e  = tid + 256 * p;       // 0..2047
        int nl = e >> 4;              // row within tile
        int j  = e & 15;              // float4 index within row
        int g  = idx_s[nl * Kn + k];
        const float* src = xb + ((size_t)g << 6) + (j << 2);
        float* dst = buf + (j >> 1) * SKK + (nl >> 3) * 64 + (j & 1) * 32 +
                     ((nl & 7) << 2);
        cp16(dst, src);
    }
}

__device__ __forceinline__ void mma8(float* d, uint32_t a0, uint32_t a1,
                                     uint32_t a2, uint32_t a3, uint32_t b0,
                                     uint32_t b1) {
    asm volatile(
        "mma.sync.aligned.m16n8k8.row.col.f32.tf32.tf32.f32 "
        "{%0,%1,%2,%3}, {%4,%5,%6,%7}, {%8,%9}, {%0,%1,%2,%3};\n"
        : "+f"(d[0]), "+f"(d[1]), "+f"(d[2]), "+f"(d[3])
        : "r"(a0), "r"(a1), "r"(a2), "r"(a3), "r"(b0), "r"(b1));
}

__device__ __forceinline__ void compute_chunk(const float* __restrict__ buf,
                                              int k, int wm, int wn, int lane,
                                              float d[2][4][4]) {
#pragma unroll
    for (int kk = 0; kk < 8; kk++) {
        int ks = k * 8 + kk;
        const uint4 A0 = __ldg(reinterpret_cast<const uint4*>(
            g_wp + (((2 * wm + 0) * 56 + ks) * 32 + lane) * 4));
        const uint4 A1 = __ldg(reinterpret_cast<const uint4*>(
            g_wp + (((2 * wm + 1) * 56 + ks) * 32 + lane) * 4));
        uint32_t b0[4], b1[4];
#pragma unroll
        for (int tt = 0; tt < 4; tt++) {
            const float* p = buf + kk * SKK + (wn * 4 + tt) * 64 + lane;
            b0[tt] = __float_as_uint(p[0]);
            b1[tt] = __float_as_uint(p[32]);
        }
#pragma unroll
        for (int tt = 0; tt < 4; tt++) {
            mma8(d[0][tt], A0.x, A0.y, A0.z, A0.w, b0[tt], b1[tt]);
            mma8(d[1][tt], A1.x, A1.y, A1.z, A1.w, b0[tt], b1[tt]);
        }
    }
}

__global__ __launch_bounds__(256, 2) void fused_kernel(
    const float* __restrict__ bias, float* __restrict__ out) {
    extern __shared__ float sm[];
    float* bp0   = sm;
    float* bp1   = bp0 + CHUNK_F;
    int*   idx_s = (int*)(bp1 + CHUNK_F);

    int tid  = threadIdx.x;
    int lane = tid & 31;
    int w    = tid >> 5;
    int wm   = w & 1;   // M half (32 rows)
    int wn   = w >> 1;  // N quarter (32 cols)
    int b    = blockIdx.y;
    int n0   = blockIdx.x * TN;
    const float* xb = g_xt + (size_t)b * Ndim * Cdim;

    // Load this tile's neighbor indices into smem.
    for (int e = tid; e < TN * Kn; e += 256) {
        int gi = n0 * Kn + e;
        idx_s[e] = (gi < KN) ? g_idx[gi] : 0;
    }
    __syncthreads();

    gather_chunk(xb, idx_s, 0, bp0, tid);
    asm volatile("cp.async.commit_group;\n");
    gather_chunk(xb, idx_s, 1, bp1, tid);
    asm volatile("cp.async.commit_group;\n");
    asm volatile("cp.async.wait_group 1;\n");
    __syncthreads();

    float d[2][4][4];
#pragma unroll
    for (int i = 0; i < 2; i++)
#pragma unroll
        for (int j = 0; j < 4; j++)
#pragma unroll
            for (int q = 0; q < 4; q++) d[i][j][q] = 0.f;

    for (int k = 0; k < Kn; k++) {
        const float* buf = (k & 1) ? bp1 : bp0;
        compute_chunk(buf, k, wm, wn, lane, d);
        __syncthreads();
        if (k + 2 < Kn) {
            float* nbuf = (k & 1) ? bp1 : bp0;  // just-freed buffer
            gather_chunk(xb, idx_s, k + 2, nbuf, tid);
            asm volatile("cp.async.commit_group;\n");
            asm volatile("cp.async.wait_group 1;\n");  // chunk k+1 complete
            __syncthreads();
        } else if (k + 1 < Kn) {
            asm volatile("cp.async.wait_group 0;\n");  // last chunk complete
            __syncthreads();
        }
    }

    // Epilogue: add bias, write out[b, o, n]
#pragma unroll
    for (int mb2 = 0; mb2 < 2; mb2++) {
        int o = wm * 32 + mb2 * 16 + (lane >> 2);
        float bv0 = bias[o];
        float bv1 = bias[o + 8];
        float* op0 = out + ((size_t)(b * OUTd + o)) * Ndim;
        float* op1 = op0 + (size_t)8 * Ndim;
#pragma unroll
        for (int tt = 0; tt < 4; tt++) {
            int nb = n0 + wn * 32 + tt * 8 + 2 * (lane & 3);
            if (nb < Ndim) {
                float v0 = d[mb2][tt][0] + bv0;
                float v1 = d[mb2][tt][1] + bv0;
                float v2 = d[mb2][tt][2] + bv1;
                float v3 = d[mb2][tt][3] + bv1;
                if (nb + 1 < Ndim) {
                    *reinterpret_cast<float2*>(op0 + nb) = make_float2(v0, v1);
                    *reinterpret_cast<float2*>(op1 + nb) = make_float2(v2, v3);
                } else {
                    op0[nb] = v0;
                    op1[nb] = v2;
                }
            }
        }
    }
}

// ---------------------------------------------------------------------------
// Launch
// ---------------------------------------------------------------------------
extern "C" void kernel_launch(void* const* d_in, const int* in_sizes, int n_in,
                              void* d_out, int out_size) {
    const float* x     = (const float*)d_in[0];
    const void*  neigh = d_in[1];          // int32 OR int64 (jax x64 trap)
    const float* W     = (const float*)d_in[2];
    const float* bias  = (const float*)d_in[3];
    float*       out   = (float*)d_out;

    cudaFuncSetAttribute(fused_kernel,
                         cudaFuncAttributeMaxDynamicSharedMemorySize,
                         SMEM_BYTES);

    idx_normalize<<<280, 256>>>(neigh);
    transpose_tf32<<<dim3((Ndim + 31) / 32, Cdim / 32, Bdim), dim3(32, 8)>>>(x);
    wprep_kernel<<<(WP_F + 255) / 256, 256>>>(W);
    fused_kernel<<<dim3(NTILES, Bdim), 256, SMEM_BYTES>>>(bias, out);
}

// round 6
// speedup vs baseline: 2.4495x; 2.1499x over previous
#include <cuda_runtime.h>
#include <cuda_fp16.h>
#include <cstdint>

// Problem constants
#define Bdim   8
#define Cdim   64
#define Ndim   40962
#define Kn     7
#define KN     (Kn * Ndim)
#define OUTd   64
#define TN     128                    // n-tile per CTA
#define NTILES ((Ndim + TN - 1) / TN) // 321

// Smem: two 16KB chunk buffers (128 rows x 128B, XOR-swizzled 16B slots) + idx
#define CHUNK_B   (TN * 128)          // 16384 bytes
#define SMEM_BYTES (2 * CHUNK_B + TN * Kn * 4)

// W fragment image: 4 mb-blocks x 28 ksteps x 32 lanes x 4 b32 (half2 pairs)
#define WP_U32  (4 * 28 * 32 * 4)     // 14336

// Device scratch (allocation-free rule). 256B-aligned for cp.async/LDG.128.
__device__ __align__(256) __half   g_xh[(size_t)Bdim * Ndim * Cdim];
__device__ __align__(256) uint32_t g_wp[WP_U32];
__device__ __align__(256) int      g_idx[KN];

__device__ __forceinline__ uint32_t smem_u32(const void* p) {
    return (uint32_t)__cvta_generic_to_shared(p);
}
__device__ __forceinline__ void cp16(void* dst, const void* src) {
    asm volatile("cp.async.cg.shared.global [%0], [%1], 16;\n"
                 ::"r"(smem_u32(dst)), "l"(src));
}
#define CP_COMMIT() asm volatile("cp.async.commit_group;\n")

// ---------------------------------------------------------------------------
// Kernel 0: normalize neighbor indices (int32 OR int64 input) -> g_idx int32.
// Dtype detected per-block: int64 input has all-zero odd int32 words in the
// first 4096; random int32 indices cannot. Deterministic, block-local.
// ---------------------------------------------------------------------------
__global__ void idx_normalize(const void* __restrict__ neigh) {
    __shared__ int s_is64;
    const int* p32 = (const int*)neigh;
    int tid = threadIdx.x;
    unsigned acc = 0;
#pragma unroll
    for (int q = 0; q < 8; q++) acc |= (unsigned)p32[2 * (tid + 256 * q) + 1];
#pragma unroll
    for (int o = 16; o > 0; o >>= 1) acc |= __shfl_down_sync(~0u, acc, o);
    if (tid == 0) s_is64 = 1;
    __syncthreads();
    if ((tid & 31) == 0 && acc != 0) s_is64 = 0;
    __syncthreads();
    int is64 = s_is64;
    const long long* p64 = (const long long*)neigh;
    for (int i = blockIdx.x * 256 + tid; i < KN; i += gridDim.x * 256)
        g_idx[i] = is64 ? (int)p64[i] : p32[i];
}

// ---------------------------------------------------------------------------
// Kernel 1: transpose x [B, C=64, N] -> g_xh [B, N, C] as fp16.
// Block: 32 n x 64 c, 256 threads.
// ---------------------------------------------------------------------------
__global__ void transpose_f16(const float* __restrict__ x) {
    __shared__ float tile[64][33];
    int b  = blockIdx.y;
    int n0 = blockIdx.x * 32;
    int t  = threadIdx.x;
    const float* xb = x + (size_t)b * Cdim * Ndim;

    int nl = t & 31, cb = t >> 5;   // load: n = n0+nl, c = cb*8 + r
#pragma unroll
    for (int r = 0; r < 8; r++) {
        int c = cb * 8 + r;
        int n = n0 + nl;
        tile[c][nl] = (n < Ndim) ? xb[(size_t)c * Ndim + n] : 0.f;
    }
    __syncthreads();
    int c2 = t & 31, nb = t >> 5;   // store: half2 col c2, n = n0 + nb + r*8
    __half2* xhb = (__half2*)(g_xh + (size_t)b * Ndim * Cdim);
#pragma unroll
    for (int r = 0; r < 4; r++) {
        int n = n0 + nb + r * 8;
        if (n < Ndim)
            xhb[(size_t)n * 32 + c2] =
                __floats2half2_rn(tile[2 * c2][nb + r * 8],
                                  tile[2 * c2 + 1][nb + r * 8]);
    }
}

// ---------------------------------------------------------------------------
// Kernel 2: pack W [64, 448] into fp16 A-fragment stream for m16n8k16.
// b32 index i = (((mb*28 + ks)*32 + lane)*4 + r), mb in 0..3 (16 rows each):
//   r=0: (o = mb*16 + lane/4,     kc = ks*16 + 2*(lane%4))      pair (kc,kc+1)
//   r=1: o+8, same kc;  r=2: same o, kc+8;  r=3: o+8, kc+8
// ---------------------------------------------------------------------------
__global__ void wprep_kernel(const float* __restrict__ W) {
    int i = blockIdx.x * 256 + threadIdx.x;
    if (i >= WP_U32) return;
    int r  = i & 3;
    int l  = (i >> 2) & 31;
    int ks = (i >> 7) % 28;
    int mb = (i >> 7) / 28;        // 0..3
    int o  = mb * 16 + (l >> 2) + (r & 1) * 8;
    int kc = ks * 16 + 2 * (l & 3) + ((r >> 1) & 1) * 8;
    __half h0 = __float2half_rn(W[o * 448 + kc]);
    __half h1 = __float2half_rn(W[o * 448 + kc + 1]);
    g_wp[i] = (uint32_t)__half_as_ushort(h0) |
              ((uint32_t)__half_as_ushort(h1) << 16);
}

// ---------------------------------------------------------------------------
// Kernel 3: fused gather + fp16 tensor-core GEMM.
// ---------------------------------------------------------------------------
// Gather chunk k into smem: row n (128B = 64 halves), 16B slot j swizzled by
// (j ^ (n&7)) for conflict-free ldmatrix.
__device__ __forceinline__ void gather_chunk(const __half* __restrict__ xb,
                                             const int* __restrict__ idx_s,
                                             int k, char* __restrict__ buf,
                                             int tid) {
#pragma unroll
    for (int p = 0; p < 4; p++) {
        int e  = tid + 256 * p;   // 0..1023
        int nl = e >> 3;          // row 0..127
        int j  = e & 7;           // 16B slot
        int g  = idx_s[nl * Kn + k];
        const __half* src = xb + ((size_t)g << 6) + (j << 3);
        char* dst = buf + nl * 128 + ((j ^ (nl & 7)) << 4);
        cp16(dst, src);
    }
}

__device__ __forceinline__ void mma16(float* d, uint32_t a0, uint32_t a1,
                                      uint32_t a2, uint32_t a3, uint32_t b0,
                                      uint32_t b1) {
    asm volatile(
        "mma.sync.aligned.m16n8k16.row.col.f32.f16.f16.f32 "
        "{%0,%1,%2,%3}, {%4,%5,%6,%7}, {%8,%9}, {%0,%1,%2,%3};\n"
        : "+f"(d[0]), "+f"(d[1]), "+f"(d[2]), "+f"(d[3])
        : "r"(a0), "r"(a1), "r"(a2), "r"(a3), "r"(b0), "r"(b1));
}

// Compute one chunk (K=64 -> 4 ksteps of k16) for this warp.
__device__ __forceinline__ void compute_chunk(uint32_t bbase, int k, int wm,
                                              int wn, int lane,
                                              float d[2][4][4]) {
    int rr = lane & 7, gA = lane >> 3;
    const uint4* wp4 = (const uint4*)g_wp;
#pragma unroll
    for (int h = 0; h < 2; h++) {
        // A fragments: ksteps ks = k*4 + 2h + {0,1}; mb-blocks 2*wm + {0,1}
        uint4 A[2][2];
#pragma unroll
        for (int mb = 0; mb < 2; mb++)
#pragma unroll
            for (int kq = 0; kq < 2; kq++) {
                int ks = k * 4 + 2 * h + kq;
                A[mb][kq] = __ldg(&wp4[((2 * wm + mb) * 28 + ks) * 32 + lane]);
            }
#pragma unroll
        for (int tt = 0; tt < 4; tt++) {
            uint32_t addr = bbase + (uint32_t)((wn * 32 + tt * 8 + rr) * 128) +
                            (uint32_t)(((4 * h + gA) ^ rr) << 4);
            uint32_t b0, b1, b2, b3;
            asm volatile(
                "ldmatrix.sync.aligned.m8n8.x4.shared.b16 {%0,%1,%2,%3}, [%4];"
                : "=r"(b0), "=r"(b1), "=r"(b2), "=r"(b3)
                : "r"(addr));
            mma16(d[0][tt], A[0][0].x, A[0][0].y, A[0][0].z, A[0][0].w, b0, b1);
            mma16(d[1][tt], A[1][0].x, A[1][0].y, A[1][0].z, A[1][0].w, b0, b1);
            mma16(d[0][tt], A[0][1].x, A[0][1].y, A[0][1].z, A[0][1].w, b2, b3);
            mma16(d[1][tt], A[1][1].x, A[1][1].y, A[1][1].z, A[1][1].w, b2, b3);
        }
    }
}

__global__ __launch_bounds__(256, 2) void fused_kernel(
    const float* __restrict__ bias, float* __restrict__ out) {
    extern __shared__ char sm[];
    char* bp[2]  = { sm, sm + CHUNK_B };
    int*  idx_s  = (int*)(sm + 2 * CHUNK_B);

    int tid  = threadIdx.x;
    int lane = tid & 31;
    int w    = tid >> 5;
    int wm   = w & 1;   // M half (32 output rows)
    int wn   = w >> 1;  // N quarter (32 n-cols)
    int b    = blockIdx.y;
    int n0   = blockIdx.x * TN;
    const __half* xb = g_xh + (size_t)b * Ndim * Cdim;

    for (int e = tid; e < TN * Kn; e += 256) {
        int gi = n0 * Kn + e;
        idx_s[e] = (gi < KN) ? g_idx[gi] : 0;
    }
    __syncthreads();

    gather_chunk(xb, idx_s, 0, bp[0], tid); CP_COMMIT();
    gather_chunk(xb, idx_s, 1, bp[1], tid); CP_COMMIT();
    asm volatile("cp.async.wait_group 1;\n");
    __syncthreads();

    float d[2][4][4];
#pragma unroll
    for (int i = 0; i < 2; i++)
#pragma unroll
        for (int j = 0; j < 4; j++)
#pragma unroll
            for (int q = 0; q < 4; q++) d[i][j][q] = 0.f;

    uint32_t bb[2] = { smem_u32(bp[0]), smem_u32(bp[1]) };

    for (int k = 0; k < Kn; k++) {
        compute_chunk(bb[k & 1], k, wm, wn, lane, d);
        __syncthreads();
        if (k + 2 < Kn) {
            gather_chunk(xb, idx_s, k + 2, bp[k & 1], tid);
            CP_COMMIT();
            asm volatile("cp.async.wait_group 1;\n");   // chunk k+1 ready
            __syncthreads();
        } else if (k + 1 < Kn) {
            asm volatile("cp.async.wait_group 0;\n");
            __syncthreads();
        }
    }

    // Epilogue: bias + store out[b, o, n]
#pragma unroll
    for (int mb2 = 0; mb2 < 2; mb2++) {
        int o = wm * 32 + mb2 * 16 + (lane >> 2);
        float bv0 = __ldg(&bias[o]);
        float bv1 = __ldg(&bias[o + 8]);
        float* op0 = out + ((size_t)(b * OUTd + o)) * Ndim;
        float* op1 = op0 + (size_t)8 * Ndim;
#pragma unroll
        for (int tt = 0; tt < 4; tt++) {
            int nb = n0 + wn * 32 + tt * 8 + 2 * (lane & 3);
            if (nb < Ndim) {
                float v0 = d[mb2][tt][0] + bv0;
                float v1 = d[mb2][tt][1] + bv0;
                float v2 = d[mb2][tt][2] + bv1;
                float v3 = d[mb2][tt][3] + bv1;
                if (nb + 1 < Ndim) {
                    *reinterpret_cast<float2*>(op0 + nb) = make_float2(v0, v1);
                    *reinterpret_cast<float2*>(op1 + nb) = make_float2(v2, v3);
                } else {
                    op0[nb] = v0;
                    op1[nb] = v2;
                }
            }
        }
    }
}

// ---------------------------------------------------------------------------
// Launch
// ---------------------------------------------------------------------------
extern "C" void kernel_launch(void* const* d_in, const int* in_sizes, int n_in,
                              void* d_out, int out_size) {
    const float* x     = (const float*)d_in[0];
    const void*  neigh = d_in[1];   // int32 OR int64 (jax x64 trap)
    const float* W     = (const float*)d_in[2];
    const float* bias  = (const float*)d_in[3];
    float*       out   = (float*)d_out;

    idx_normalize<<<280, 256>>>(neigh);
    transpose_f16<<<dim3((Ndim + 31) / 32, Bdim), 256>>>(x);
    wprep_kernel<<<(WP_U32 + 255) / 256, 256>>>(W);
    fused_kernel<<<dim3(NTILES, Bdim), 256, SMEM_BYTES>>>(bias, out);
}

// round 7
// speedup vs baseline: 2.6171x; 1.0684x over previous
#include <cuda_runtime.h>
#include <cuda_fp16.h>
#include <cstdint>

// Problem constants
#define Bdim   8
#define Cdim   64
#define Ndim   40962
#define Kn     7
#define KN     (Kn * Ndim)
#define OUTd   64
#define TN     128                    // n-tile per CTA
#define NTILES ((Ndim + TN - 1) / TN) // 321

// Smem: four 16KB chunk buffers (128 rows x 128B, XOR-swizzled 16B slots) + idx
#define CHUNK_B    (TN * 128)         // 16384 bytes
#define NSTAGE     4
#define SMEM_BYTES (NSTAGE * CHUNK_B + TN * Kn * 4)   // 69,120 B

// W fragment image: 4 mb-blocks x 28 ksteps x 32 lanes x 4 b32 (half2 pairs)
#define WP_U32  (4 * 28 * 32 * 4)     // 14336
#define WP_BLOCKS ((WP_U32 + 255) / 256)  // 56

// Device scratch (allocation-free rule). 256B-aligned for cp.async/LDG.128.
__device__ __align__(256) __half   g_xh[(size_t)Bdim * Ndim * Cdim];
__device__ __align__(256) uint32_t g_wp[WP_U32];
__device__ __align__(256) int      g_idx[KN];

__device__ __forceinline__ uint32_t smem_u32(const void* p) {
    return (uint32_t)__cvta_generic_to_shared(p);
}
__device__ __forceinline__ void cp16(void* dst, const void* src) {
    asm volatile("cp.async.cg.shared.global [%0], [%1], 16;\n"
                 ::"r"(smem_u32(dst)), "l"(src));
}
#define CP_COMMIT() asm volatile("cp.async.commit_group;\n")

// ---------------------------------------------------------------------------
// Kernel 0: combined prep.
//  blocks [0, WP_BLOCKS): pack W [64,448] into fp16 A-fragment stream.
//  blocks [WP_BLOCKS, +280): normalize neighbor indices (int32 OR int64).
// ---------------------------------------------------------------------------
__global__ void prep_kernel(const void* __restrict__ neigh,
                            const float* __restrict__ W) {
    int tid = threadIdx.x;
    if (blockIdx.x < WP_BLOCKS) {
        int i = blockIdx.x * 256 + tid;
        if (i >= WP_U32) return;
        int r  = i & 3;
        int l  = (i >> 2) & 31;
        int ks = (i >> 7) % 28;
        int mb = (i >> 7) / 28;        // 0..3
        int o  = mb * 16 + (l >> 2) + (r & 1) * 8;
        int kc = ks * 16 + 2 * (l & 3) + ((r >> 1) & 1) * 8;
        __half h0 = __float2half_rn(W[o * 448 + kc]);
        __half h1 = __float2half_rn(W[o * 448 + kc + 1]);
        g_wp[i] = (uint32_t)__half_as_ushort(h0) |
                  ((uint32_t)__half_as_ushort(h1) << 16);
        return;
    }
    // --- idx normalize. Dtype detected per-block: int64 input has all-zero
    // odd int32 words in the first 4096; random int32 indices cannot.
    __shared__ int s_is64;
    const int* p32 = (const int*)neigh;
    unsigned acc = 0;
#pragma unroll
    for (int q = 0; q < 8; q++) acc |= (unsigned)p32[2 * (tid + 256 * q) + 1];
#pragma unroll
    for (int o = 16; o > 0; o >>= 1) acc |= __shfl_down_sync(~0u, acc, o);
    if (tid == 0) s_is64 = 1;
    __syncthreads();
    if ((tid & 31) == 0 && acc != 0) s_is64 = 0;
    __syncthreads();
    int is64 = s_is64;
    const long long* p64 = (const long long*)neigh;
    int bx = blockIdx.x - WP_BLOCKS;
    for (int i = bx * 256 + tid; i < KN; i += 280 * 256)
        g_idx[i] = is64 ? (int)p64[i] : p32[i];
}

// ---------------------------------------------------------------------------
// Kernel 1: transpose x [B, C=64, N] -> g_xh [B, N, C] as fp16.
// Block: 32 n x 64 c, 256 threads.
// ---------------------------------------------------------------------------
__global__ void transpose_f16(const float* __restrict__ x) {
    __shared__ float tile[64][33];
    int b  = blockIdx.y;
    int n0 = blockIdx.x * 32;
    int t  = threadIdx.x;
    const float* xb = x + (size_t)b * Cdim * Ndim;

    int nl = t & 31, cb = t >> 5;   // load: n = n0+nl, c = cb*8 + r
#pragma unroll
    for (int r = 0; r < 8; r++) {
        int c = cb * 8 + r;
        int n = n0 + nl;
        tile[c][nl] = (n < Ndim) ? xb[(size_t)c * Ndim + n] : 0.f;
    }
    __syncthreads();
    int c2 = t & 31, nb = t >> 5;   // store: half2 col c2, n = n0 + nb + r*8
    __half2* xhb = (__half2*)(g_xh + (size_t)b * Ndim * Cdim);
#pragma unroll
    for (int r = 0; r < 4; r++) {
        int n = n0 + nb + r * 8;
        if (n < Ndim)
            xhb[(size_t)n * 32 + c2] =
                __floats2half2_rn(tile[2 * c2][nb + r * 8],
                                  tile[2 * c2 + 1][nb + r * 8]);
    }
}

// ---------------------------------------------------------------------------
// Kernel 2: fused gather + fp16 tensor-core GEMM, 4-stage pipeline.
// ---------------------------------------------------------------------------
// Gather chunk k into smem: row n (128B = 64 halves), 16B slot j swizzled by
// (j ^ (n&7)) for conflict-free ldmatrix.
__device__ __forceinline__ void gather_chunk(const __half* __restrict__ xb,
                                             const int* __restrict__ idx_s,
                                             int k, char* __restrict__ buf,
                                             int tid) {
#pragma unroll
    for (int p = 0; p < 4; p++) {
        int e  = tid + 256 * p;   // 0..1023
        int nl = e >> 3;          // row 0..127
        int j  = e & 7;           // 16B slot
        int g  = idx_s[nl * Kn + k];
        const __half* src = xb + ((size_t)g << 6) + (j << 3);
        char* dst = buf + nl * 128 + ((j ^ (nl & 7)) << 4);
        cp16(dst, src);
    }
}

__device__ __forceinline__ void mma16(float* d, uint32_t a0, uint32_t a1,
                                      uint32_t a2, uint32_t a3, uint32_t b0,
                                      uint32_t b1) {
    asm volatile(
        "mma.sync.aligned.m16n8k16.row.col.f32.f16.f16.f32 "
        "{%0,%1,%2,%3}, {%4,%5,%6,%7}, {%8,%9}, {%0,%1,%2,%3};\n"
        : "+f"(d[0]), "+f"(d[1]), "+f"(d[2]), "+f"(d[3])
        : "r"(a0), "r"(a1), "r"(a2), "r"(a3), "r"(b0), "r"(b1));
}

// Compute one chunk (K=64 -> 4 ksteps of k16) for this warp.
// All 8 A-fragment loads hoisted to chunk start to overlap the smem stream.
__device__ __forceinline__ void compute_chunk(uint32_t bbase, int k, int wm,
                                              int wn, int lane,
                                              float d[2][4][4]) {
    int rr = lane & 7, gA = lane >> 3;
    const uint4* wp4 = (const uint4*)g_wp;
    uint4 A[2][2][2];   // [h][mb][kq]
#pragma unroll
    for (int h = 0; h < 2; h++)
#pragma unroll
        for (int mb = 0; mb < 2; mb++)
#pragma unroll
            for (int kq = 0; kq < 2; kq++) {
                int ks = k * 4 + 2 * h + kq;
                A[h][mb][kq] =
                    __ldg(&wp4[((2 * wm + mb) * 28 + ks) * 32 + lane]);
            }
#pragma unroll
    for (int h = 0; h < 2; h++) {
#pragma unroll
        for (int tt = 0; tt < 4; tt++) {
            uint32_t addr = bbase + (uint32_t)((wn * 32 + tt * 8 + rr) * 128) +
                            (uint32_t)(((4 * h + gA) ^ rr) << 4);
            uint32_t b0, b1, b2, b3;
            asm volatile(
                "ldmatrix.sync.aligned.m8n8.x4.shared.b16 {%0,%1,%2,%3}, [%4];"
                : "=r"(b0), "=r"(b1), "=r"(b2), "=r"(b3)
                : "r"(addr));
            mma16(d[0][tt], A[h][0][0].x, A[h][0][0].y, A[h][0][0].z,
                  A[h][0][0].w, b0, b1);
            mma16(d[1][tt], A[h][1][0].x, A[h][1][0].y, A[h][1][0].z,
                  A[h][1][0].w, b0, b1);
            mma16(d[0][tt], A[h][0][1].x, A[h][0][1].y, A[h][0][1].z,
                  A[h][0][1].w, b2, b3);
            mma16(d[1][tt], A[h][1][1].x, A[h][1][1].y, A[h][1][1].z,
                  A[h][1][1].w, b2, b3);
        }
    }
}

__global__ __launch_bounds__(256, 2) void fused_kernel(
    const float* __restrict__ bias, float* __restrict__ out) {
    extern __shared__ char sm[];
    int* idx_s = (int*)(sm + NSTAGE * CHUNK_B);

    int tid  = threadIdx.x;
    int lane = tid & 31;
    int w    = tid >> 5;
    int wm   = w & 1;   // M half (32 output rows)
    int wn   = w >> 1;  // N quarter (32 n-cols)
    int b    = blockIdx.y;
    int n0   = blockIdx.x * TN;
    const __half* xb = g_xh + (size_t)b * Ndim * Cdim;

    for (int e = tid; e < TN * Kn; e += 256) {
        int gi = n0 * Kn + e;
        idx_s[e] = (gi < KN) ? g_idx[gi] : 0;
    }
    __syncthreads();

    // Prologue: 3 chunks in flight.
    gather_chunk(xb, idx_s, 0, sm + 0 * CHUNK_B, tid); CP_COMMIT();
    gather_chunk(xb, idx_s, 1, sm + 1 * CHUNK_B, tid); CP_COMMIT();
    gather_chunk(xb, idx_s, 2, sm + 2 * CHUNK_B, tid); CP_COMMIT();

    float d[2][4][4];
#pragma unroll
    for (int i = 0; i < 2; i++)
#pragma unroll
        for (int j = 0; j < 4; j++)
#pragma unroll
            for (int q = 0; q < 4; q++) d[i][j][q] = 0.f;

    uint32_t bb = smem_u32(sm);

#pragma unroll
    for (int k = 0; k < Kn; k++) {
        // Need chunk k complete; allow younger gathers to stay in flight.
        if (k < 5)      asm volatile("cp.async.wait_group 2;\n");
        else if (k == 5) asm volatile("cp.async.wait_group 1;\n");
        else             asm volatile("cp.async.wait_group 0;\n");
        __syncthreads();
        compute_chunk(bb + (uint32_t)((k & 3) * CHUNK_B), k, wm, wn, lane, d);
        __syncthreads();   // all warps done with chunk k; buf (k+3)&3 is free
        if (k + 3 < Kn) {
            gather_chunk(xb, idx_s, k + 3, sm + ((k + 3) & 3) * CHUNK_B, tid);
            CP_COMMIT();
        }
    }

    // Epilogue: bias + store out[b, o, n]
#pragma unroll
    for (int mb2 = 0; mb2 < 2; mb2++) {
        int o = wm * 32 + mb2 * 16 + (lane >> 2);
        float bv0 = __ldg(&bias[o]);
        float bv1 = __ldg(&bias[o + 8]);
        float* op0 = out + ((size_t)(b * OUTd + o)) * Ndim;
        float* op1 = op0 + (size_t)8 * Ndim;
#pragma unroll
        for (int tt = 0; tt < 4; tt++) {
            int nb = n0 + wn * 32 + tt * 8 + 2 * (lane & 3);
            if (nb < Ndim) {
                float v0 = d[mb2][tt][0] + bv0;
                float v1 = d[mb2][tt][1] + bv0;
                float v2 = d[mb2][tt][2] + bv1;
                float v3 = d[mb2][tt][3] + bv1;
                if (nb + 1 < Ndim) {
                    *reinterpret_cast<float2*>(op0 + nb) = make_float2(v0, v1);
                    *reinterpret_cast<float2*>(op1 + nb) = make_float2(v2, v3);
                } else {
                    op0[nb] = v0;
                    op1[nb] = v2;
                }
            }
        }
    }
}

// ---------------------------------------------------------------------------
// Launch
// ---------------------------------------------------------------------------
extern "C" void kernel_launch(void* const* d_in, const int* in_sizes, int n_in,
                              void* d_out, int out_size) {
    const float* x     = (const float*)d_in[0];
    const void*  neigh = d_in[1];   // int32 OR int64 (jax x64 trap)
    const float* W     = (const float*)d_in[2];
    const float* bias  = (const float*)d_in[3];
    float*       out   = (float*)d_out;

    cudaFuncSetAttribute(fused_kernel,
                         cudaFuncAttributeMaxDynamicSharedMemorySize,
                         SMEM_BYTES);

    prep_kernel<<<WP_BLOCKS + 280, 256>>>(neigh, W);
    transpose_f16<<<dim3((Ndim + 31) / 32, Bdim), 256>>>(x);
    fused_kernel<<<dim3(NTILES, Bdim), 256, SMEM_BYTES>>>(bias, out);
}

// round 9
// speedup vs baseline: 2.7215x; 1.0399x over previous
#include <cuda_runtime.h>
#include <cuda_fp16.h>
#include <cstdint>

// Problem constants
#define Bdim   8
#define Cdim   64
#define Ndim   40962
#define Kn     7
#define KN     (Kn * Ndim)
#define OUTd   64
#define TN     128                    // n-tile per CTA
#define NTILES ((Ndim + TN - 1) / TN) // 321

// Smem: four 16KB chunk buffers (128 rows x 128B, XOR-swizzled 16B slots) + idx
#define CHUNK_B    (TN * 128)         // 16384 bytes
#define NSTAGE     4
#define SMEM_BYTES (NSTAGE * CHUNK_B + TN * Kn * 4)   // 69,120 B

// W fragment image: 4 mb-blocks x 28 ksteps x 32 lanes x 4 b32 (half2 pairs)
#define WP_U32    (4 * 28 * 32 * 4)   // 14336
#define WP_BLOCKS ((WP_U32 + 255) / 256)  // 56

// Combined prep grid ranges
#define NB32     ((Ndim + 31) / 32)   // 1281 transpose column-blocks per batch
#define TBLOCKS  (NB32 * Bdim)        // 10248
#define IBLOCKS  280

// Device scratch (allocation-free rule). 256B-aligned for cp.async/LDG.128.
__device__ __align__(256) __half   g_xh[(size_t)Bdim * Ndim * Cdim];
__device__ __align__(256) uint32_t g_wp[WP_U32];
__device__ __align__(256) int      g_idx[KN];

__device__ __forceinline__ uint32_t smem_u32(const void* p) {
    return (uint32_t)__cvta_generic_to_shared(p);
}
__device__ __forceinline__ void cp16(void* dst, const void* src) {
    asm volatile("cp.async.cg.shared.global [%0], [%1], 16;\n"
                 ::"r"(smem_u32(dst)), "l"(src));
}
#define CP_COMMIT() asm volatile("cp.async.commit_group;\n")

// ---------------------------------------------------------------------------
// Kernel 0: combined prep (transpose + W pack + idx normalize), one launch.
//  blocks [0, TBLOCKS): transpose x [B,C,N] -> g_xh [B,N,C] fp16
//  blocks [TBLOCKS, +WP_BLOCKS): pack W into fp16 A-fragment stream
//  blocks [TBLOCKS+WP_BLOCKS, +IBLOCKS): normalize neigh (int32 OR int64)
// ---------------------------------------------------------------------------
__global__ void prep_kernel(const float* __restrict__ x,
                            const void* __restrict__ neigh,
                            const float* __restrict__ W) {
    int tid = threadIdx.x;

    if (blockIdx.x < TBLOCKS) {
        // ---- transpose: 32 n x 64 c tile, smem round trip ----
        __shared__ float tile[64][33];
        int b  = blockIdx.x / NB32;
        int n0 = (blockIdx.x % NB32) * 32;
        const float* xb = x + (size_t)b * Cdim * Ndim;

        int nl = tid & 31, cb = tid >> 5;   // load: n = n0+nl, c = cb*8 + r
#pragma unroll
        for (int r = 0; r < 8; r++) {
            int c = cb * 8 + r;
            int n = n0 + nl;
            tile[c][nl] = (n < Ndim) ? xb[(size_t)c * Ndim + n] : 0.f;
        }
        __syncthreads();
        int c2 = tid & 31, nb = tid >> 5;   // store: half2 col c2
        __half2* xhb = (__half2*)(g_xh + (size_t)b * Ndim * Cdim);
#pragma unroll
        for (int r = 0; r < 4; r++) {
            int n = n0 + nb + r * 8;
            if (n < Ndim)
                xhb[(size_t)n * 32 + c2] =
                    __floats2half2_rn(tile[2 * c2][nb + r * 8],
                                      tile[2 * c2 + 1][nb + r * 8]);
        }
        return;
    }

    if (blockIdx.x < TBLOCKS + WP_BLOCKS) {
        // ---- W pack: b32 i = (((mb*28+ks)*32+lane)*4 + r) ----
        int i = (blockIdx.x - TBLOCKS) * 256 + tid;
        if (i >= WP_U32) return;
        int r  = i & 3;
        int l  = (i >> 2) & 31;
        int ks = (i >> 7) % 28;
        int mb = (i >> 7) / 28;        // 0..3
        int o  = mb * 16 + (l >> 2) + (r & 1) * 8;
        int kc = ks * 16 + 2 * (l & 3) + ((r >> 1) & 1) * 8;
        __half h0 = __float2half_rn(W[o * 448 + kc]);
        __half h1 = __float2half_rn(W[o * 448 + kc + 1]);
        g_wp[i] = (uint32_t)__half_as_ushort(h0) |
                  ((uint32_t)__half_as_ushort(h1) << 16);
        return;
    }

    // ---- idx normalize. Dtype detected per-block: int64 input has all-zero
    // odd int32 words in the first 4096; random int32 indices cannot. ----
    __shared__ int s_is64;
    const int* p32 = (const int*)neigh;
    unsigned acc = 0;
#pragma unroll
    for (int q = 0; q < 8; q++) acc |= (unsigned)p32[2 * (tid + 256 * q) + 1];
#pragma unroll
    for (int o = 16; o > 0; o >>= 1) acc |= __shfl_down_sync(~0u, acc, o);
    if (tid == 0) s_is64 = 1;
    __syncthreads();
    if ((tid & 31) == 0 && acc != 0) s_is64 = 0;
    __syncthreads();
    int is64 = s_is64;
    const long long* p64 = (const long long*)neigh;
    int bx = blockIdx.x - TBLOCKS - WP_BLOCKS;
    for (int i = bx * 256 + tid; i < KN; i += IBLOCKS * 256)
        g_idx[i] = is64 ? (int)p64[i] : p32[i];
}

// ---------------------------------------------------------------------------
// Kernel 1: fused gather + fp16 tensor-core GEMM, 4-stage pipeline,
// single barrier per chunk.
// ---------------------------------------------------------------------------
// Gather chunk k into smem: row n (128B = 64 halves), 16B slot j swizzled by
// (j ^ (n&7)) for conflict-free ldmatrix.
__device__ __forceinline__ void gather_chunk(const __half* __restrict__ xb,
                                             const int* __restrict__ idx_s,
                                             int k, char* __restrict__ buf,
                                             int tid) {
#pragma unroll
    for (int p = 0; p < 4; p++) {
        int e  = tid + 256 * p;   // 0..1023
        int nl = e >> 3;          // row 0..127
        int j  = e & 7;           // 16B slot
        int g  = idx_s[nl * Kn + k];
        const __half* src = xb + ((size_t)g << 6) + (j << 3);
        char* dst = buf + nl * 128 + ((j ^ (nl & 7)) << 4);
        cp16(dst, src);
    }
}

__device__ __forceinline__ void mma16(float* d, uint32_t a0, uint32_t a1,
                                      uint32_t a2, uint32_t a3, uint32_t b0,
                                      uint32_t b1) {
    asm volatile(
        "mma.sync.aligned.m16n8k16.row.col.f32.f16.f16.f32 "
        "{%0,%1,%2,%3}, {%4,%5,%6,%7}, {%8,%9}, {%0,%1,%2,%3};\n"
        : "+f"(d[0]), "+f"(d[1]), "+f"(d[2]), "+f"(d[3])
        : "r"(a0), "r"(a1), "r"(a2), "r"(a3), "r"(b0), "r"(b1));
}

// Compute one chunk (K=64 -> 4 ksteps of k16) for this warp.
// All 8 A-fragment loads hoisted to chunk start to overlap the smem stream.
__device__ __forceinline__ void compute_chunk(uint32_t bbase, int k, int wm,
                                              int wn, int lane,
                                              float d[2][4][4]) {
    int rr = lane & 7, gA = lane >> 3;
    const uint4* wp4 = (const uint4*)g_wp;
    uint4 A[2][2][2];   // [h][mb][kq]
#pragma unroll
    for (int h = 0; h < 2; h++)
#pragma unroll
        for (int mb = 0; mb < 2; mb++)
#pragma unroll
            for (int kq = 0; kq < 2; kq++) {
                int ks = k * 4 + 2 * h + kq;
                A[h][mb][kq] =
                    __ldg(&wp4[((2 * wm + mb) * 28 + ks) * 32 + lane]);
            }
#pragma unroll
    for (int h = 0; h < 2; h++) {
#pragma unroll
        for (int tt = 0; tt < 4; tt++) {
            uint32_t addr = bbase + (uint32_t)((wn * 32 + tt * 8 + rr) * 128) +
                            (uint32_t)(((4 * h + gA) ^ rr) << 4);
            uint32_t b0, b1, b2, b3;
            asm volatile(
                "ldmatrix.sync.aligned.m8n8.x4.shared.b16 {%0,%1,%2,%3}, [%4];"
                : "=r"(b0), "=r"(b1), "=r"(b2), "=r"(b3)
                : "r"(addr));
            mma16(d[0][tt], A[h][0][0].x, A[h][0][0].y, A[h][0][0].z,
                  A[h][0][0].w, b0, b1);
            mma16(d[1][tt], A[h][1][0].x, A[h][1][0].y, A[h][1][0].z,
                  A[h][1][0].w, b0, b1);
            mma16(d[0][tt], A[h][0][1].x, A[h][0][1].y, A[h][0][1].z,
                  A[h][0][1].w, b2, b3);
            mma16(d[1][tt], A[h][1][1].x, A[h][1][1].y, A[h][1][1].z,
                  A[h][1][1].w, b2, b3);
        }
    }
}

__global__ __launch_bounds__(256, 2) void fused_kernel(
    const float* __restrict__ bias, float* __restrict__ out) {
    extern __shared__ char sm[];
    int* idx_s = (int*)(sm + NSTAGE * CHUNK_B);

    int tid  = threadIdx.x;
    int lane = tid & 31;
    int w    = tid >> 5;
    int wm   = w & 1;   // M half (32 output rows)
    int wn   = w >> 1;  // N quarter (32 n-cols)
    int b    = blockIdx.y;
    int n0   = blockIdx.x * TN;
    const __half* xb = g_xh + (size_t)b * Ndim * Cdim;

    for (int e = tid; e < TN * Kn; e += 256) {
        int gi = n0 * Kn + e;
        idx_s[e] = (gi < KN) ? g_idx[gi] : 0;
    }
    __syncthreads();

    // Prologue: 3 chunks in flight.
    gather_chunk(xb, idx_s, 0, sm + 0 * CHUNK_B, tid); CP_COMMIT();
    gather_chunk(xb, idx_s, 1, sm + 1 * CHUNK_B, tid); CP_COMMIT();
    gather_chunk(xb, idx_s, 2, sm + 2 * CHUNK_B, tid); CP_COMMIT();

    float d[2][4][4];
#pragma unroll
    for (int i = 0; i < 2; i++)
#pragma unroll
        for (int j = 0; j < 4; j++)
#pragma unroll
            for (int q = 0; q < 4; q++) d[i][j][q] = 0.f;

    uint32_t bb = smem_u32(sm);

#pragma unroll
    for (int k = 0; k < Kn; k++) {
        // Chunk k must be complete; younger gathers may remain in flight.
        if (k < 5)       asm volatile("cp.async.wait_group 2;\n");
        else if (k == 5) asm volatile("cp.async.wait_group 1;\n");
        else             asm volatile("cp.async.wait_group 0;\n");
        // This barrier makes chunk k visible to all warps AND proves every
        // warp finished reading chunk k-1 -> buffer (k+3)&3 == (k-1)&3 is
        // free to overwrite. Single barrier per chunk.
        __syncthreads();
        if (k + 3 < Kn) {
            gather_chunk(xb, idx_s, k + 3, sm + ((k + 3) & 3) * CHUNK_B, tid);
            CP_COMMIT();
        }
        compute_chunk(bb + (uint32_t)((k & 3) * CHUNK_B), k, wm, wn, lane, d);
    }

    // Epilogue: bias + store out[b, o, n] (accumulators are warp-local).
#pragma unroll
    for (int mb2 = 0; mb2 < 2; mb2++) {
        int o = wm * 32 + mb2 * 16 + (lane >> 2);
        float bv0 = __ldg(&bias[o]);
        float bv1 = __ldg(&bias[o + 8]);
        float* op0 = out + ((size_t)(b * OUTd + o)) * Ndim;
        float* op1 = op0 + (size_t)8 * Ndim;
#pragma unroll
        for (int tt = 0; tt < 4; tt++) {
            int nb = n0 + wn * 32 + tt * 8 + 2 * (lane & 3);
            if (nb < Ndim) {
                float v0 = d[mb2][tt][0] + bv0;
                float v1 = d[mb2][tt][1] + bv0;
                float v2 = d[mb2][tt][2] + bv1;
                float v3 = d[mb2][tt][3] + bv1;
                if (nb + 1 < Ndim) {
                    *reinterpret_cast<float2*>(op0 + nb) = make_float2(v0, v1);
                    *reinterpret_cast<float2*>(op1 + nb) = make_float2(v2, v3);
                } else {
                    op0[nb] = v0;
                    op1[nb] = v2;
                }
            }
        }
    }
}

// ---------------------------------------------------------------------------
// Launch
// ---------------------------------------------------------------------------
extern "C" void kernel_launch(void* const* d_in, const int* in_sizes, int n_in,
                              void* d_out, int out_size) {
    const float* x     = (const float*)d_in[0];
    const void*  neigh = d_in[1];   // int32 OR int64 (jax x64 trap)
    const float* W     = (const float*)d_in[2];
    const float* bias  = (const float*)d_in[3];
    float*       out   = (float*)d_out;

    cudaFuncSetAttribute(fused_kernel,
                         cudaFuncAttributeMaxDynamicSharedMemorySize,
                         SMEM_BYTES);

    prep_kernel<<<TBLOCKS + WP_BLOCKS + IBLOCKS, 256>>>(x, neigh, W);
    fused_kernel<<<dim3(NTILES, Bdim), 256, SMEM_BYTES>>>(bias, out);
}

// round 12
// speedup vs baseline: 2.7318x; 1.0038x over previous
#include <cuda_runtime.h>
#include <cuda_fp16.h>
#include <cstdint>

// Problem constants
#define Bdim   8
#define Cdim   64
#define Ndim   40962
#define Kn     7
#define KN     (Kn * Ndim)
#define OUTd   64
#define TN     128                    // n-tile per CTA
#define NTILES ((Ndim + TN - 1) / TN) // 321

// Smem: five 16KB chunk buffers (128 rows x 128B, XOR-swizzled 16B slots) + idx
#define CHUNK_B    (TN * 128)         // 16384 bytes
#define NSTAGE     5
#define SMEM_BYTES (NSTAGE * CHUNK_B + TN * Kn * 4)   // 85,504 B (2 CTAs/SM)

// W fragment image: 4 mb-blocks x 28 ksteps x 32 lanes x 4 b32 (half2 pairs)
#define WP_U32    (4 * 28 * 32 * 4)   // 14336
#define WP_BLOCKS ((WP_U32 + 255) / 256)  // 56

// Combined prep grid ranges
#define NB32     ((Ndim + 31) / 32)   // 1281 transpose column-blocks per batch
#define TBLOCKS  (NB32 * Bdim)        // 10248
#define IBLOCKS  280

// Device scratch (allocation-free rule). 256B-aligned for cp.async/LDG.128.
__device__ __align__(256) __half   g_xh[(size_t)Bdim * Ndim * Cdim];
__device__ __align__(256) uint32_t g_wp[WP_U32];
__device__ __align__(256) int      g_idx[KN];

__device__ __forceinline__ uint32_t smem_u32(const void* p) {
    return (uint32_t)__cvta_generic_to_shared(p);
}
__device__ __forceinline__ void cp16(void* dst, const void* src) {
    asm volatile("cp.async.cg.shared.global [%0], [%1], 16;\n"
                 ::"r"(smem_u32(dst)), "l"(src));
}
#define CP_COMMIT() asm volatile("cp.async.commit_group;\n")

// ---------------------------------------------------------------------------
// Kernel 0: combined prep (transpose + W pack + idx normalize), one launch.
//  blocks [0, TBLOCKS): transpose x [B,C,N] -> g_xh [B,N,C] fp16
//  blocks [TBLOCKS, +WP_BLOCKS): pack W into fp16 A-fragment stream
//  blocks [TBLOCKS+WP_BLOCKS, +IBLOCKS): normalize neigh (int32 OR int64)
// ---------------------------------------------------------------------------
__global__ void prep_kernel(const float* __restrict__ x,
                            const void* __restrict__ neigh,
                            const float* __restrict__ W) {
    int tid = threadIdx.x;

    if (blockIdx.x < TBLOCKS) {
        // ---- transpose: 32 n x 64 c tile, smem round trip ----
        __shared__ float tile[64][33];
        int b  = blockIdx.x / NB32;
        int n0 = (blockIdx.x % NB32) * 32;
        const float* xb = x + (size_t)b * Cdim * Ndim;

        int nl = tid & 31, cb = tid >> 5;   // load: n = n0+nl, c = cb*8 + r
#pragma unroll
        for (int r = 0; r < 8; r++) {
            int c = cb * 8 + r;
            int n = n0 + nl;
            tile[c][nl] = (n < Ndim) ? xb[(size_t)c * Ndim + n] : 0.f;
        }
        __syncthreads();
        int c2 = tid & 31, nb = tid >> 5;   // store: half2 col c2
        __half2* xhb = (__half2*)(g_xh + (size_t)b * Ndim * Cdim);
#pragma unroll
        for (int r = 0; r < 4; r++) {
            int n = n0 + nb + r * 8;
            if (n < Ndim)
                xhb[(size_t)n * 32 + c2] =
                    __floats2half2_rn(tile[2 * c2][nb + r * 8],
                                      tile[2 * c2 + 1][nb + r * 8]);
        }
        return;
    }

    if (blockIdx.x < TBLOCKS + WP_BLOCKS) {
        // ---- W pack: b32 i = (((mb*28+ks)*32+lane)*4 + r) ----
        int i = (blockIdx.x - TBLOCKS) * 256 + tid;
        if (i >= WP_U32) return;
        int r  = i & 3;
        int l  = (i >> 2) & 31;
        int ks = (i >> 7) % 28;
        int mb = (i >> 7) / 28;        // 0..3
        int o  = mb * 16 + (l >> 2) + (r & 1) * 8;
        int kc = ks * 16 + 2 * (l & 3) + ((r >> 1) & 1) * 8;
        __half h0 = __float2half_rn(W[o * 448 + kc]);
        __half h1 = __float2half_rn(W[o * 448 + kc + 1]);
        g_wp[i] = (uint32_t)__half_as_ushort(h0) |
                  ((uint32_t)__half_as_ushort(h1) << 16);
        return;
    }

    // ---- idx normalize. Dtype detected per-block: int64 input has all-zero
    // odd int32 words in the first 4096; random int32 indices cannot. ----
    __shared__ int s_is64;
    const int* p32 = (const int*)neigh;
    unsigned acc = 0;
#pragma unroll
    for (int q = 0; q < 8; q++) acc |= (unsigned)p32[2 * (tid + 256 * q) + 1];
#pragma unroll
    for (int o = 16; o > 0; o >>= 1) acc |= __shfl_down_sync(~0u, acc, o);
    if (tid == 0) s_is64 = 1;
    __syncthreads();
    if ((tid & 31) == 0 && acc != 0) s_is64 = 0;
    __syncthreads();
    int is64 = s_is64;
    const long long* p64 = (const long long*)neigh;
    int bx = blockIdx.x - TBLOCKS - WP_BLOCKS;
    for (int i = bx * 256 + tid; i < KN; i += IBLOCKS * 256)
        g_idx[i] = is64 ? (int)p64[i] : p32[i];
}

// ---------------------------------------------------------------------------
// Kernel 1: fused gather + fp16 tensor-core GEMM, 5-stage pipeline,
// single barrier per chunk, 16o x 64n warp tiles (halved A-fragment traffic).
// ---------------------------------------------------------------------------
// Gather chunk k into smem: row n (128B = 64 halves), 16B slot j swizzled by
// (j ^ (n&7)) for conflict-free ldmatrix.
__device__ __forceinline__ void gather_chunk(const __half* __restrict__ xb,
                                             const int* __restrict__ idx_s,
                                             int k, char* __restrict__ buf,
                                             int tid) {
#pragma unroll
    for (int p = 0; p < 4; p++) {
        int e  = tid + 256 * p;   // 0..1023
        int nl = e >> 3;          // row 0..127
        int j  = e & 7;           // 16B slot
        int g  = idx_s[nl * Kn + k];
        const __half* src = xb + ((size_t)g << 6) + (j << 3);
        char* dst = buf + nl * 128 + ((j ^ (nl & 7)) << 4);
        cp16(dst, src);
    }
}

__device__ __forceinline__ void mma16(float* d, uint32_t a0, uint32_t a1,
                                      uint32_t a2, uint32_t a3, uint32_t b0,
                                      uint32_t b1) {
    asm volatile(
        "mma.sync.aligned.m16n8k16.row.col.f32.f16.f16.f32 "
        "{%0,%1,%2,%3}, {%4,%5,%6,%7}, {%8,%9}, {%0,%1,%2,%3};\n"
        : "+f"(d[0]), "+f"(d[1]), "+f"(d[2]), "+f"(d[3])
        : "r"(a0), "r"(a1), "r"(a2), "r"(a3), "r"(b0), "r"(b1));
}

// Compute one chunk (K=64 -> 4 ksteps of k16) for this warp.
// Warp tile: 16 output rows (mb = wm) x 64 n-cols (half wq).
// 4 A-fragment LDG.128 per chunk (each mb fetched by only 2 warps).
__device__ __forceinline__ void compute_chunk(uint32_t bbase, int k, int wm,
                                              int wq, int lane,
                                              float d[8][4]) {
    int rr = lane & 7, gA = lane >> 3;
    const uint4* wp4 = (const uint4*)g_wp;
    uint4 A[2][2];   // [h][kq]
#pragma unroll
    for (int h = 0; h < 2; h++)
#pragma unroll
        for (int kq = 0; kq < 2; kq++) {
            int ks = k * 4 + 2 * h + kq;
            A[h][kq] = __ldg(&wp4[(wm * 28 + ks) * 32 + lane]);
        }
#pragma unroll
    for (int h = 0; h < 2; h++) {
#pragma unroll
        for (int tt = 0; tt < 8; tt++) {
            uint32_t addr = bbase + (uint32_t)((wq * 64 + tt * 8 + rr) * 128) +
                            (uint32_t)(((4 * h + gA) ^ rr) << 4);
            uint32_t b0, b1, b2, b3;
            asm volatile(
                "ldmatrix.sync.aligned.m8n8.x4.shared.b16 {%0,%1,%2,%3}, [%4];"
                : "=r"(b0), "=r"(b1), "=r"(b2), "=r"(b3)
                : "r"(addr));
            mma16(d[tt], A[h][0].x, A[h][0].y, A[h][0].z, A[h][0].w, b0, b1);
            mma16(d[tt], A[h][1].x, A[h][1].y, A[h][1].z, A[h][1].w, b2, b3);
        }
    }
}

__global__ __launch_bounds__(256, 2) void fused_kernel(
    const float* __restrict__ bias, float* __restrict__ out) {
    extern __shared__ char sm[];
    int* idx_s = (int*)(sm + NSTAGE * CHUNK_B);

    int tid  = threadIdx.x;
    int lane = tid & 31;
    int w    = tid >> 5;
    int wm   = w & 3;   // mb block: output rows [16*wm, 16*wm+16)
    int wq   = w >> 2;  // n half: cols [64*wq, 64*wq+64)
    int b    = blockIdx.y;
    int n0   = blockIdx.x * TN;
    const __half* xb = g_xh + (size_t)b * Ndim * Cdim;

    for (int e = tid; e < TN * Kn; e += 256) {
        int gi = n0 * Kn + e;
        idx_s[e] = (gi < KN) ? g_idx[gi] : 0;
    }
    __syncthreads();

    // Prologue: 4 chunks in flight.
    gather_chunk(xb, idx_s, 0, sm + 0 * CHUNK_B, tid); CP_COMMIT();
    gather_chunk(xb, idx_s, 1, sm + 1 * CHUNK_B, tid); CP_COMMIT();
    gather_chunk(xb, idx_s, 2, sm + 2 * CHUNK_B, tid); CP_COMMIT();
    gather_chunk(xb, idx_s, 3, sm + 3 * CHUNK_B, tid); CP_COMMIT();

    float d[8][4];
#pragma unroll
    for (int j = 0; j < 8; j++)
#pragma unroll
        for (int q = 0; q < 4; q++) d[j][q] = 0.f;

    uint32_t bb = smem_u32(sm);

#pragma unroll
    for (int k = 0; k < Kn; k++) {
        // Chunk k must be complete; younger gathers may remain in flight.
        if (k <= 3)      asm volatile("cp.async.wait_group 3;\n");
        else if (k == 4) asm volatile("cp.async.wait_group 2;\n");
        else if (k == 5) asm volatile("cp.async.wait_group 1;\n");
        else             asm volatile("cp.async.wait_group 0;\n");
        // Barrier makes chunk k visible AND proves all warps finished chunk
        // k-1, so buffer (k+4)%5 == (k-1)%5 is free. One barrier per chunk.
        __syncthreads();
        if (k + 4 < Kn) {
            gather_chunk(xb, idx_s, k + 4, sm + ((k + 4) % NSTAGE) * CHUNK_B,
                         tid);
            CP_COMMIT();
        }
        compute_chunk(bb + (uint32_t)((k % NSTAGE) * CHUNK_B), k, wm, wq,
                      lane, d);
    }

    // Epilogue: bias + store out[b, o, n] (accumulators are warp-local).
    {
        int o = wm * 16 + (lane >> 2);
        float bv0 = __ldg(&bias[o]);
        float bv1 = __ldg(&bias[o + 8]);
        float* op0 = out + ((size_t)(b * OUTd + o)) * Ndim;
        float* op1 = op0 + (size_t)8 * Ndim;
#pragma unroll
        for (int tt = 0; tt < 8; tt++) {
            int nb = n0 + wq * 64 + tt * 8 + 2 * (lane & 3);
            if (nb < Ndim) {
                float v0 = d[tt][0] + bv0;
                float v1 = d[tt][1] + bv0;
                float v2 = d[tt][2] + bv1;
                float v3 = d[tt][3] + bv1;
                if (nb + 1 < Ndim) {
                    *reinterpret_cast<float2*>(op0 + nb) = make_float2(v0, v1);
                    *reinterpret_cast<float2*>(op1 + nb) = make_float2(v2, v3);
                } else {
                    op0[nb] = v0;
                    op1[nb] = v2;
                }
            }
        }
    }
}

// ---------------------------------------------------------------------------
// Launch
// ---------------------------------------------------------------------------
extern "C" void kernel_launch(void* const* d_in, const int* in_sizes, int n_in,
                              void* d_out, int out_size) {
    const float* x     = (const float*)d_in[0];
    const void*  neigh = d_in[1];   // int32 OR int64 (jax x64 trap)
    const float* W     = (const float*)d_in[2];
    const float* bias  = (const float*)d_in[3];
    float*       out   = (float*)d_out;

    cudaFuncSetAttribute(fused_kernel,
                         cudaFuncAttributeMaxDynamicSharedMemorySize,
                         SMEM_BYTES);

    prep_kernel<<<TBLOCKS + WP_BLOCKS + IBLOCKS, 256>>>(x, neigh, W);
    fused_kernel<<<dim3(NTILES, Bdim), 256, SMEM_BYTES>>>(bias, out);
}

// round 13
// speedup vs baseline: 2.9782x; 1.0902x over previous
#include <cuda_runtime.h>
#include <cuda_fp16.h>
#include <cstdint>

// Problem constants
#define Bdim   8
#define Cdim   64
#define Ndim   40962
#define Kn     7
#define KN     (Kn * Ndim)
#define OUTd   64
#define TN     128                    // n-tile per CTA
#define NTILES ((Ndim + TN - 1) / TN) // 321

// Smem: four 16KB chunk buffers (128 rows x 128B, XOR-swizzled 16B slots) + idx
#define CHUNK_B    (TN * 128)         // 16384 bytes
#define NSTAGE     4
#define SMEM_BYTES (NSTAGE * CHUNK_B + TN * Kn * 4)   // 69,120 B -> 3 CTAs/SM

// W fragment image: 4 mb-blocks x 28 ksteps x 32 lanes x 4 b32 (half2 pairs)
#define WP_U32    (4 * 28 * 32 * 4)   // 14336
#define WP_BLOCKS ((WP_U32 + 255) / 256)  // 56

// Combined prep grid ranges
#define NB32     ((Ndim + 31) / 32)   // 1281 transpose column-blocks per batch
#define TBLOCKS  (NB32 * Bdim)        // 10248
#define IBLOCKS  280

// Device scratch (allocation-free rule). 256B-aligned for cp.async/LDG.128.
__device__ __align__(256) __half   g_xh[(size_t)Bdim * Ndim * Cdim];
__device__ __align__(256) uint32_t g_wp[WP_U32];
__device__ __align__(256) int      g_idx[KN];

__device__ __forceinline__ uint32_t smem_u32(const void* p) {
    return (uint32_t)__cvta_generic_to_shared(p);
}
__device__ __forceinline__ void cp16(void* dst, const void* src) {
    asm volatile("cp.async.cg.shared.global [%0], [%1], 16;\n"
                 ::"r"(smem_u32(dst)), "l"(src));
}
#define CP_COMMIT() asm volatile("cp.async.commit_group;\n")

// ---------------------------------------------------------------------------
// Kernel 0: combined prep (transpose + W pack + idx normalize), one launch.
//  blocks [0, TBLOCKS): transpose x [B,C,N] -> g_xh [B,N,C] fp16
//  blocks [TBLOCKS, +WP_BLOCKS): pack W into fp16 A-fragment stream
//  blocks [TBLOCKS+WP_BLOCKS, +IBLOCKS): normalize neigh (int32 OR int64)
// ---------------------------------------------------------------------------
__global__ void prep_kernel(const float* __restrict__ x,
                            const void* __restrict__ neigh,
                            const float* __restrict__ W) {
    int tid = threadIdx.x;

    if (blockIdx.x < TBLOCKS) {
        // ---- transpose: 32 n x 64 c tile, smem round trip ----
        __shared__ float tile[64][33];
        int b  = blockIdx.x / NB32;
        int n0 = (blockIdx.x % NB32) * 32;
        const float* xb = x + (size_t)b * Cdim * Ndim;

        int nl = tid & 31, cb = tid >> 5;   // load: n = n0+nl, c = cb*8 + r
#pragma unroll
        for (int r = 0; r < 8; r++) {
            int c = cb * 8 + r;
            int n = n0 + nl;
            tile[c][nl] = (n < Ndim) ? xb[(size_t)c * Ndim + n] : 0.f;
        }
        __syncthreads();
        int c2 = tid & 31, nb = tid >> 5;   // store: half2 col c2
        __half2* xhb = (__half2*)(g_xh + (size_t)b * Ndim * Cdim);
#pragma unroll
        for (int r = 0; r < 4; r++) {
            int n = n0 + nb + r * 8;
            if (n < Ndim)
                xhb[(size_t)n * 32 + c2] =
                    __floats2half2_rn(tile[2 * c2][nb + r * 8],
                                      tile[2 * c2 + 1][nb + r * 8]);
        }
        return;
    }

    if (blockIdx.x < TBLOCKS + WP_BLOCKS) {
        // ---- W pack: b32 i = (((mb*28+ks)*32+lane)*4 + r) ----
        int i = (blockIdx.x - TBLOCKS) * 256 + tid;
        if (i >= WP_U32) return;
        int r  = i & 3;
        int l  = (i >> 2) & 31;
        int ks = (i >> 7) % 28;
        int mb = (i >> 7) / 28;        // 0..3
        int o  = mb * 16 + (l >> 2) + (r & 1) * 8;
        int kc = ks * 16 + 2 * (l & 3) + ((r >> 1) & 1) * 8;
        __half h0 = __float2half_rn(W[o * 448 + kc]);
        __half h1 = __float2half_rn(W[o * 448 + kc + 1]);
        g_wp[i] = (uint32_t)__half_as_ushort(h0) |
                  ((uint32_t)__half_as_ushort(h1) << 16);
        return;
    }

    // ---- idx normalize. Dtype detected per-block: int64 input has all-zero
    // odd int32 words in the first 4096; random int32 indices cannot. ----
    __shared__ int s_is64;
    const int* p32 = (const int*)neigh;
    unsigned acc = 0;
#pragma unroll
    for (int q = 0; q < 8; q++) acc |= (unsigned)p32[2 * (tid + 256 * q) + 1];
#pragma unroll
    for (int o = 16; o > 0; o >>= 1) acc |= __shfl_down_sync(~0u, acc, o);
    if (tid == 0) s_is64 = 1;
    __syncthreads();
    if ((tid & 31) == 0 && acc != 0) s_is64 = 0;
    __syncthreads();
    int is64 = s_is64;
    const long long* p64 = (const long long*)neigh;
    int bx = blockIdx.x - TBLOCKS - WP_BLOCKS;
    for (int i = bx * 256 + tid; i < KN; i += IBLOCKS * 256)
        g_idx[i] = is64 ? (int)p64[i] : p32[i];
}

// ---------------------------------------------------------------------------
// Kernel 1: fused gather + fp16 tensor-core GEMM, 4-stage pipeline,
// single barrier per chunk, 32o x 32n warp tiles (optimal fragment traffic:
// m_tiles*16KB + n_tiles*8KB minimized at (2,4)), 3 CTAs/SM.
// ---------------------------------------------------------------------------
// Gather chunk k into smem: row n (128B = 64 halves), 16B slot j swizzled by
// (j ^ (n&7)) for conflict-free ldmatrix.
__device__ __forceinline__ void gather_chunk(const __half* __restrict__ xb,
                                             const int* __restrict__ idx_s,
                                             int k, char* __restrict__ buf,
                                             int tid) {
#pragma unroll
    for (int p = 0; p < 4; p++) {
        int e  = tid + 256 * p;   // 0..1023
        int nl = e >> 3;          // row 0..127
        int j  = e & 7;           // 16B slot
        int g  = idx_s[nl * Kn + k];
        const __half* src = xb + ((size_t)g << 6) + (j << 3);
        char* dst = buf + nl * 128 + ((j ^ (nl & 7)) << 4);
        cp16(dst, src);
    }
}

__device__ __forceinline__ void mma16(float* d, uint32_t a0, uint32_t a1,
                                      uint32_t a2, uint32_t a3, uint32_t b0,
                                      uint32_t b1) {
    asm volatile(
        "mma.sync.aligned.m16n8k16.row.col.f32.f16.f16.f32 "
        "{%0,%1,%2,%3}, {%4,%5,%6,%7}, {%8,%9}, {%0,%1,%2,%3};\n"
        : "+f"(d[0]), "+f"(d[1]), "+f"(d[2]), "+f"(d[3])
        : "r"(a0), "r"(a1), "r"(a2), "r"(a3), "r"(b0), "r"(b1));
}

// Compute one chunk (K=64 -> 4 ksteps of k16) for this warp.
// Warp tile: 32 output rows (mb pair 2*wm..) x 32 n-cols (quarter wn).
// A loaded per-h (4 live uint4 = 16 regs) to keep total regs under the
// 85-reg cap for 3 CTAs/SM.
__device__ __forceinline__ void compute_chunk(uint32_t bbase, int k, int wm,
                                              int wn, int lane,
                                              float d[2][4][4]) {
    int rr = lane & 7, gA = lane >> 3;
    const uint4* wp4 = (const uint4*)g_wp;
#pragma unroll
    for (int h = 0; h < 2; h++) {
        uint4 A[2][2];   // [mb][kq]
#pragma unroll
        for (int mb = 0; mb < 2; mb++)
#pragma unroll
            for (int kq = 0; kq < 2; kq++) {
                int ks = k * 4 + 2 * h + kq;
                A[mb][kq] =
                    __ldg(&wp4[((2 * wm + mb) * 28 + ks) * 32 + lane]);
            }
#pragma unroll
        for (int tt = 0; tt < 4; tt++) {
            uint32_t addr = bbase + (uint32_t)((wn * 32 + tt * 8 + rr) * 128) +
                            (uint32_t)(((4 * h + gA) ^ rr) << 4);
            uint32_t b0, b1, b2, b3;
            asm volatile(
                "ldmatrix.sync.aligned.m8n8.x4.shared.b16 {%0,%1,%2,%3}, [%4];"
                : "=r"(b0), "=r"(b1), "=r"(b2), "=r"(b3)
                : "r"(addr));
            mma16(d[0][tt], A[0][0].x, A[0][0].y, A[0][0].z, A[0][0].w, b0, b1);
            mma16(d[1][tt], A[1][0].x, A[1][0].y, A[1][0].z, A[1][0].w, b0, b1);
            mma16(d[0][tt], A[0][1].x, A[0][1].y, A[0][1].z, A[0][1].w, b2, b3);
            mma16(d[1][tt], A[1][1].x, A[1][1].y, A[1][1].z, A[1][1].w, b2, b3);
        }
    }
}

__global__ __launch_bounds__(256, 3) void fused_kernel(
    const float* __restrict__ bias, float* __restrict__ out) {
    extern __shared__ char sm[];
    int* idx_s = (int*)(sm + NSTAGE * CHUNK_B);

    int tid  = threadIdx.x;
    int lane = tid & 31;
    int w    = tid >> 5;
    int wm   = w & 1;   // M half (32 output rows)
    int wn   = w >> 1;  // N quarter (32 n-cols)
    int b    = blockIdx.y;
    int n0   = blockIdx.x * TN;
    const __half* xb = g_xh + (size_t)b * Ndim * Cdim;

    for (int e = tid; e < TN * Kn; e += 256) {
        int gi = n0 * Kn + e;
        idx_s[e] = (gi < KN) ? g_idx[gi] : 0;
    }
    __syncthreads();

    // Prologue: 3 chunks in flight.
    gather_chunk(xb, idx_s, 0, sm + 0 * CHUNK_B, tid); CP_COMMIT();
    gather_chunk(xb, idx_s, 1, sm + 1 * CHUNK_B, tid); CP_COMMIT();
    gather_chunk(xb, idx_s, 2, sm + 2 * CHUNK_B, tid); CP_COMMIT();

    float d[2][4][4];
#pragma unroll
    for (int i = 0; i < 2; i++)
#pragma unroll
        for (int j = 0; j < 4; j++)
#pragma unroll
            for (int q = 0; q < 4; q++) d[i][j][q] = 0.f;

    uint32_t bb = smem_u32(sm);

#pragma unroll
    for (int k = 0; k < Kn; k++) {
        // Chunk k must be complete; younger gathers may remain in flight.
        if (k < 5)       asm volatile("cp.async.wait_group 2;\n");
        else if (k == 5) asm volatile("cp.async.wait_group 1;\n");
        else             asm volatile("cp.async.wait_group 0;\n");
        // Barrier makes chunk k visible AND proves all warps finished chunk
        // k-1, so buffer (k+3)&3 == (k-1)&3 is free. One barrier per chunk.
        __syncthreads();
        if (k + 3 < Kn) {
            gather_chunk(xb, idx_s, k + 3, sm + ((k + 3) & 3) * CHUNK_B, tid);
            CP_COMMIT();
        }
        compute_chunk(bb + (uint32_t)((k & 3) * CHUNK_B), k, wm, wn, lane, d);
    }

    // Epilogue: bias + store out[b, o, n] (accumulators are warp-local).
#pragma unroll
    for (int mb2 = 0; mb2 < 2; mb2++) {
        int o = wm * 32 + mb2 * 16 + (lane >> 2);
        float bv0 = __ldg(&bias[o]);
        float bv1 = __ldg(&bias[o + 8]);
        float* op0 = out + ((size_t)(b * OUTd + o)) * Ndim;
        float* op1 = op0 + (size_t)8 * Ndim;
#pragma unroll
        for (int tt = 0; tt < 4; tt++) {
            int nb = n0 + wn * 32 + tt * 8 + 2 * (lane & 3);
            if (nb < Ndim) {
                float v0 = d[mb2][tt][0] + bv0;
                float v1 = d[mb2][tt][1] + bv0;
                float v2 = d[mb2][tt][2] + bv1;
                float v3 = d[mb2][tt][3] + bv1;
                if (nb + 1 < Ndim) {
                    *reinterpret_cast<float2*>(op0 + nb) = make_float2(v0, v1);
                    *reinterpret_cast<float2*>(op1 + nb) = make_float2(v2, v3);
                } else {
                    op0[nb] = v0;
                    op1[nb] = v2;
                }
            }
        }
    }
}

// ---------------------------------------------------------------------------
// Launch
// ---------------------------------------------------------------------------
extern "C" void kernel_launch(void* const* d_in, const int* in_sizes, int n_in,
                              void* d_out, int out_size) {
    const float* x     = (const float*)d_in[0];
    const void*  neigh = d_in[1];   // int32 OR int64 (jax x64 trap)
    const float* W     = (const float*)d_in[2];
    const float* bias  = (const float*)d_in[3];
    float*       out   = (float*)d_out;

    cudaFuncSetAttribute(fused_kernel,
                         cudaFuncAttributeMaxDynamicSharedMemorySize,
                         SMEM_BYTES);

    prep_kernel<<<TBLOCKS + WP_BLOCKS + IBLOCKS, 256>>>(x, neigh, W);
    fused_kernel<<<dim3(NTILES, Bdim), 256, SMEM_BYTES>>>(bias, out);
}